// round 4
// baseline (speedup 1.0000x reference)
#include <cuda_runtime.h>
#include <cuda_bf16.h>
#include <cstdint>

#define NUM_CLASSES 100000
#define EMBED 512
#define BATCH_N 4096
#define LAMBDA_C 0.01f
#define ALPHA_C 0.1f

// Per-class linked lists of sample indices (scratch; rebuilt every call).
__device__ int g_head[NUM_CLASSES];
__device__ int g_next[BATCH_N];

// build per-class chains (duplicates accumulate via the chain) + zero loss
__global__ __launch_bounds__(256)
void build_kernel(const int* __restrict__ y, float* __restrict__ loss) {
    int i = blockIdx.x * blockDim.x + threadIdx.x;
    if (i == 0) *loss = 0.0f;
    if (i < BATCH_N) {
        int c = y[i];
        int old = atomicExch(&g_head[c], i);
        g_next[i] = old;
    }
}

// fused copy + apply: one streaming pass over all centers.
// 256 threads = 2 class rows per block; 128 threads / row, one float4 each.
__global__ __launch_bounds__(256)
void fused_copy_apply_kernel(const float4* __restrict__ centers4,
                             const float4* __restrict__ batch4,
                             float* __restrict__ dst,
                             float* __restrict__ loss) {
    const int row = blockIdx.x * 2 + (threadIdx.x >> 7);
    const int t   = threadIdx.x & 127;          // float4 index within row

    float4 c4 = __ldcs(centers4 + (size_t)row * (EMBED / 4) + t);
    int h = g_head[row];                        // uniform per half-block
    float4 v = c4;

    if (h >= 0) {
        float ax = 0.f, ay = 0.f, az = 0.f, aw = 0.f, ls = 0.f;
        int s = h;
        while (s >= 0) {
            float4 b4 = batch4[(size_t)s * (EMBED / 4) + t];
            float dx = b4.x - c4.x;
            float dy = b4.y - c4.y;
            float dz = b4.z - c4.z;
            float dw = b4.w - c4.w;
            ax += dx; ay += dy; az += dz; aw += dw;
            ls += dx * dx + dy * dy + dz * dz + dw * dw;
            s = g_next[s];
        }
        v.x += ALPHA_C * ax;
        v.y += ALPHA_C * ay;
        v.z += ALPHA_C * az;
        v.w += ALPHA_C * aw;

        // warp-level loss reduce (chain membership is uniform per 128-thread
        // row, hence uniform per warp)
        #pragma unroll
        for (int off = 16; off > 0; off >>= 1)
            ls += __shfl_xor_sync(0xFFFFFFFFu, ls, off);
        if ((t & 31) == 0)
            atomicAdd(loss, ls * (LAMBDA_C / (float)BATCH_N));
    }

    // dst row is misaligned by 4B (out+1) -> scalar stores
    float* d = dst + (size_t)row * EMBED + t * 4;
    __stcs(d + 0, v.x);
    __stcs(d + 1, v.y);
    __stcs(d + 2, v.z);
    __stcs(d + 3, v.w);
}

extern "C" void kernel_launch(void* const* d_in, const int* in_sizes, int n_in,
                              void* d_out, int out_size) {
    const int*   y       = (const int*)d_in[0];
    const float* batch   = (const float*)d_in[1];
    const float* centers = (const float*)d_in[2];

    float* out = (float*)d_out;
    const size_t ncs = (size_t)NUM_CLASSES * EMBED;

    float* loss_ptr;
    float* new_centers;
    if (out_size == (int)(ncs + 1)) {
        loss_ptr = out;
        new_centers = out + 1;
    } else {
        new_centers = out;
        loss_ptr = out + ncs;
    }

    // 1) reset heads to -1 via memset node (0xFF bytes == -1 as int)
    void* head_ptr = nullptr;
    cudaGetSymbolAddress(&head_ptr, g_head);
    cudaMemsetAsync(head_ptr, 0xFF, NUM_CLASSES * sizeof(int), 0);

    // 2) build chains + zero loss
    build_kernel<<<(BATCH_N + 255) / 256, 256>>>(y, loss_ptr);

    // 3) fused streaming copy + apply
    fused_copy_apply_kernel<<<NUM_CLASSES / 2, 256>>>(
        reinterpret_cast<const float4*>(centers),
        reinterpret_cast<const float4*>(batch),
        new_centers, loss_ptr);
}